// round 14
// baseline (speedup 1.0000x reference)
#include <cuda_runtime.h>
#include <math.h>
#include <stdint.h>

// ---- problem constants ----
#define S_    4
#define C_    1024
#define N_    131072
#define DK_   128
#define DA_   2048
#define MTOP_ 32
#define KMAX_ 64
#define B_    64
#define NPC_  (N_ / C_)        // 128
#define M_    (MTOP_ * NPC_)   // 4096
#define T_    1.0f
#define EPS_  1e-8f

// ---- device scratch (allocation-free rule: __device__ globals) ----
__device__ float g_w[S_];
__device__ float g_qn[S_ * B_ * DK_];            // [s][b][k]
__device__ float g_cn[S_ * C_ * DK_];            // normalized centroids
__device__ float g_cscore[B_ * C_];
__device__ int   g_topc[B_ * MTOP_];
__device__ float g_sif[(size_t)B_ * N_];         // s_i_full, 33.5 MB

// =====================================================================
// K0: w = softmax(aspect_weights)
// =====================================================================
__global__ void k_weights(const float* __restrict__ aw) {
    if (threadIdx.x == 0) {
        float m = aw[0];
        for (int s = 1; s < S_; ++s) m = fmaxf(m, aw[s]);
        float e[S_]; float sum = 0.f;
        for (int s = 0; s < S_; ++s) { e[s] = expf(aw[s] - m); sum += e[s]; }
        for (int s = 0; s < S_; ++s) g_w[s] = e[s] / sum;
    }
}

// =====================================================================
// K1: queries[b,s,:] = W_Q[s] @ z[b], then L2-normalize over k.
// grid (B_, S_), 256 threads.
// =====================================================================
__global__ void k_queries(const float* __restrict__ z, const float* __restrict__ WQ) {
    __shared__ float sz[DA_];
    __shared__ float qsh[DK_];
    __shared__ float red[9];
    const int b = blockIdx.x, s = blockIdx.y;
    const int tid = threadIdx.x, lane = tid & 31, warp = tid >> 5;

    for (int i = tid; i < DA_; i += 256) sz[i] = z[(size_t)b * DA_ + i];
    __syncthreads();

    const float4* sz4 = (const float4*)sz;
    for (int k = warp; k < DK_; k += 8) {
        const float4* Wr = (const float4*)(WQ + ((size_t)s * DK_ + k) * DA_);
        float acc = 0.f;
        for (int i = lane; i < DA_ / 4; i += 32) {
            float4 w4 = Wr[i], z4 = sz4[i];
            acc += w4.x * z4.x + w4.y * z4.y + w4.z * z4.z + w4.w * z4.w;
        }
        for (int o = 16; o; o >>= 1) acc += __shfl_xor_sync(0xffffffffu, acc, o);
        if (lane == 0) qsh[k] = acc;
    }
    __syncthreads();

    float v = (tid < DK_) ? qsh[tid] : 0.f;
    float ss = v * v;
    for (int o = 16; o; o >>= 1) ss += __shfl_xor_sync(0xffffffffu, ss, o);
    if (lane == 0) red[warp] = ss;
    __syncthreads();
    if (tid == 0) {
        float t = 0.f;
        for (int w = 0; w < 8; ++w) t += red[w];
        red[8] = 1.f / (sqrtf(t) + EPS_);
    }
    __syncthreads();
    if (tid < DK_) g_qn[((size_t)s * B_ + b) * DK_ + tid] = qsh[tid] * red[8];
}

// =====================================================================
// K2: normalize centroids. grid S_*C_, 128 threads.
// =====================================================================
__global__ void k_cnorm(const float* __restrict__ cen) {
    __shared__ float red[5];
    const int row = blockIdx.x, tid = threadIdx.x;
    float v = cen[(size_t)row * DK_ + tid];
    float ss = v * v;
    for (int o = 16; o; o >>= 1) ss += __shfl_xor_sync(0xffffffffu, ss, o);
    if ((tid & 31) == 0) red[tid >> 5] = ss;
    __syncthreads();
    if (tid == 0) {
        float t = red[0] + red[1] + red[2] + red[3];
        red[4] = 1.f / (sqrtf(t) + EPS_);
    }
    __syncthreads();
    g_cn[(size_t)row * DK_ + tid] = v * red[4];
}

// =====================================================================
// K3: c_score[b,c] = sum_s w_s * (qn[b,s] . cn[s,c]). grid B_, 256 thr.
// =====================================================================
__global__ void k_cscore() {
    __shared__ float qw[S_ * DK_];
    const int b = blockIdx.x, tid = threadIdx.x;
    for (int i = tid; i < S_ * DK_; i += 256) {
        int s = i >> 7;
        qw[i] = g_w[s] * g_qn[((size_t)s * B_ + b) * DK_ + (i & 127)];
    }
    __syncthreads();
    const float4* qw4 = (const float4*)qw;
    for (int c = tid; c < C_; c += 256) {
        float acc = 0.f;
        for (int s = 0; s < S_; ++s) {
            const float4* cp = (const float4*)(g_cn + ((size_t)s * C_ + c) * DK_);
#pragma unroll
            for (int i = 0; i < 32; ++i) {
                float4 cv = cp[i]; float4 qv = qw4[s * 32 + i];
                acc += cv.x * qv.x + cv.y * qv.y + cv.z * qv.z + cv.w * qv.w;
            }
        }
        g_cscore[b * C_ + c] = acc;
    }
}

// =====================================================================
// K4: top-32 clusters per batch row (descending, tie -> lowest index,
// matching jax.lax.top_k). grid B_, 256 threads.
// =====================================================================
__global__ void k_topc() {
    __shared__ float buf[C_];
    __shared__ float rv[256];
    __shared__ int   ri[256];
    const int b = blockIdx.x, tid = threadIdx.x;
    for (int i = tid; i < C_; i += 256) buf[i] = g_cscore[b * C_ + i];
    __syncthreads();
    for (int m = 0; m < MTOP_; ++m) {
        float bv = -3.4e38f; int bi = 0;
        for (int i = tid; i < C_; i += 256) {
            float v = buf[i];
            if (v > bv) { bv = v; bi = i; }       // ascending scan keeps earliest on ties
        }
        rv[tid] = bv; ri[tid] = bi;
        __syncthreads();
        for (int off = 128; off; off >>= 1) {
            if (tid < off) {
                float v = rv[tid + off]; int j = ri[tid + off];
                if (v > rv[tid] || (v == rv[tid] && j < ri[tid])) { rv[tid] = v; ri[tid] = j; }
            }
            __syncthreads();
        }
        if (tid == 0) { g_topc[b * MTOP_ + m] = ri[0]; buf[ri[0]] = -3.4e38f; }
        __syncthreads();
    }
}

// =====================================================================
// K5 (dominant): dense pass.
// s_i_full[b,n] = sum_s (w_s*qn[b,s]) . (key[s,n]/(||key||+eps))
// grid = N/128, 256 threads, 64x128 output tile, 4x8 per-thread tile.
// Keys tile XOR-swizzled in smem; keys normalized in place; queries
// pre-scaled by w_s so all 4 aspects accumulate into one register tile.
// =====================================================================
#define SMEM_DENSE ((128 * 68 + 128 * 128 + 128) * 4)

__global__ void __launch_bounds__(256, 2) k_dense(const float* __restrict__ keys) {
    extern __shared__ float sm[];
    float*  sA    = sm;                              // [k=128][68]  (pad 4, f4-aligned)
    float4* sB4   = (float4*)(sm + 128 * 68);        // 128 n x 32 kc, swizzled
    float*  snorm = sm + 128 * 68 + 128 * 128;       // [128]
    const int tid  = threadIdx.x;
    const int lane = tid & 31, warp = tid >> 5;
    const int n0   = blockIdx.x * 128;
    const int bx   = tid & 15, by = tid >> 4;
    const int sw   = bx & 7;

    float acc[4][8];
#pragma unroll
    for (int i = 0; i < 4; ++i)
#pragma unroll
        for (int j = 0; j < 8; ++j) acc[i][j] = 0.f;

    for (int s = 0; s < S_; ++s) {
        const float ws = g_w[s];
        // queries (pre-scaled by w_s), transposed: sA[k][b]
        for (int i = tid; i < B_ * DK_; i += 256) {
            int b = i >> 7, k = i & 127;
            sA[k * 68 + b] = ws * g_qn[((size_t)s * B_ + b) * DK_ + k];
        }
        // keys tile: [n][k], float4-coalesced, xor-swizzled on kc
        const float4* kp = (const float4*)(keys + ((size_t)s * N_ + n0) * DK_);
#pragma unroll
        for (int r = 0; r < 16; ++r) {
            int i = tid + r * 256;
            int n = i >> 5, kc = i & 31;
            sB4[n * 32 + (kc ^ ((n >> 3) & 7))] = kp[i];
        }
        __syncthreads();
        // per-key inverse norms: one warp per 16 n, lane = kc (conflict-free)
        for (int n = warp; n < 128; n += 8) {
            int sw2 = (n >> 3) & 7;
            float4 v = sB4[n * 32 + (lane ^ sw2)];
            float ssq = v.x * v.x + v.y * v.y + v.z * v.z + v.w * v.w;
            for (int o = 16; o; o >>= 1) ssq += __shfl_xor_sync(0xffffffffu, ssq, o);
            if (lane == 0) snorm[n] = 1.f / (sqrtf(ssq) + EPS_);
        }
        __syncthreads();
        // normalize keys in place
#pragma unroll
        for (int r = 0; r < 16; ++r) {
            int i = tid + r * 256;
            int n = i >> 5, kc = i & 31;
            int idx = n * 32 + (kc ^ ((n >> 3) & 7));
            float inv = snorm[n];
            float4 v = sB4[idx];
            v.x *= inv; v.y *= inv; v.z *= inv; v.w *= inv;
            sB4[idx] = v;
        }
        __syncthreads();
        // 64x128x128 FMA tile
        const float4* A4 = (const float4*)sA;        // 17 float4 per k-row
#pragma unroll 4
        for (int k4 = 0; k4 < 32; ++k4) {
            float4 kb[8];
#pragma unroll
            for (int j = 0; j < 8; ++j)
                kb[j] = sB4[(bx * 8 + j) * 32 + (k4 ^ sw)];
#pragma unroll
            for (int u = 0; u < 4; ++u) {
                float4 a = A4[(k4 * 4 + u) * 17 + by];
#pragma unroll
                for (int j = 0; j < 8; ++j) {
                    float kv = (u == 0) ? kb[j].x : (u == 1) ? kb[j].y : (u == 2) ? kb[j].z : kb[j].w;
                    acc[0][j] += a.x * kv;
                    acc[1][j] += a.y * kv;
                    acc[2][j] += a.z * kv;
                    acc[3][j] += a.w * kv;
                }
            }
        }
        __syncthreads();
    }
#pragma unroll
    for (int i = 0; i < 4; ++i) {
        int b = by * 4 + i;
        float4* dst = (float4*)(g_sif + (size_t)b * N_ + n0 + bx * 8);
        dst[0] = make_float4(acc[i][0], acc[i][1], acc[i][2], acc[i][3]);
        dst[1] = make_float4(acc[i][4], acc[i][5], acc[i][6], acc[i][7]);
    }
}

// =====================================================================
// K6: soft_full = softmax(s_i_full / T) per row. grid B_, 1024 threads.
// =====================================================================
__global__ void k_softfull(float* __restrict__ out) {
    __shared__ float red[32];
    __shared__ float sM, sS;
    const int b = blockIdx.x, tid = threadIdx.x, lane = tid & 31, warp = tid >> 5;
    const float* row = g_sif + (size_t)b * N_;
    float* o = out + (size_t)(2 * B_ * KMAX_) + (size_t)b * N_;
    const float invT = 1.0f / T_;

    float m = -3.4e38f;
    for (int i = tid; i < N_; i += 1024) m = fmaxf(m, row[i]);
    for (int off = 16; off; off >>= 1) m = fmaxf(m, __shfl_xor_sync(0xffffffffu, m, off));
    if (lane == 0) red[warp] = m;
    __syncthreads();
    if (tid == 0) {
        float t = red[0];
        for (int w = 1; w < 32; ++w) t = fmaxf(t, red[w]);
        sM = t;
    }
    __syncthreads();
    const float M = sM;

    float ssum = 0.f;
    for (int i = tid; i < N_; i += 1024) ssum += expf((row[i] - M) * invT);
    for (int off = 16; off; off >>= 1) ssum += __shfl_xor_sync(0xffffffffu, ssum, off);
    if (lane == 0) red[warp] = ssum;
    __syncthreads();
    if (tid == 0) {
        float t = 0.f;
        for (int w = 0; w < 32; ++w) t += red[w];
        sS = 1.f / t;
    }
    __syncthreads();
    const float rS = sS;
    for (int i = tid; i < N_; i += 1024) o[i] = expf((row[i] - M) * invT) * rS;
}

// =====================================================================
// K7: refine path. s_i = gather(s_i_full, cand_idx); gate+exp; normalize;
// top-64 (stable); alphas + global_idx. grid B_, 256 threads.
// =====================================================================
__global__ void k_refine(const float* __restrict__ taup, const float* __restrict__ lamp,
                         const int* __restrict__ warmp, float* __restrict__ out) {
    __shared__ float raw[M_];
    __shared__ float rv[256];
    __shared__ int   ri[256];
    __shared__ float selv[KMAX_];
    __shared__ int   selj[KMAX_];
    __shared__ float sred;
    const int b = blockIdx.x, tid = threadIdx.x;
    const int warm = *warmp;
    const float tau = *taup, lam = *lamp;
    const float invT = 1.0f / T_;

    for (int j = tid; j < M_; j += 256) {
        int c = g_topc[b * MTOP_ + (j >> 7)];
        int n = c * NPC_ + (j & (NPC_ - 1));
        float si = g_sif[(size_t)b * N_ + n];
        float val;
        if (warm) {
            val = si;
        } else {
            float gg = 1.f / (1.f + expf(-lam * (si - tau)));
            val = gg * expf(si * invT);
        }
        raw[j] = val;
    }
    __syncthreads();

    if (!warm) {
        float ps = 0.f;
        for (int j = tid; j < M_; j += 256) ps += raw[j];
        for (int o = 16; o; o >>= 1) ps += __shfl_xor_sync(0xffffffffu, ps, o);
        if ((tid & 31) == 0) rv[tid >> 5] = ps;
        __syncthreads();
        if (tid == 0) {
            float t = 0.f;
            for (int w = 0; w < 8; ++w) t += rv[w];
            sred = t;
        }
        __syncthreads();
        float S1 = sred + EPS_;
        for (int j = tid; j < M_; j += 256) raw[j] = raw[j] / S1;
        __syncthreads();
    }

    // top-64, descending, tie -> lowest index (matches jax.lax.top_k)
    for (int m = 0; m < KMAX_; ++m) {
        float bv = -3.4e38f; int bi = 0;
        for (int j = tid; j < M_; j += 256) {
            float v = raw[j];
            if (v > bv) { bv = v; bi = j; }
        }
        rv[tid] = bv; ri[tid] = bi;
        __syncthreads();
        for (int off = 128; off; off >>= 1) {
            if (tid < off) {
                float v = rv[tid + off]; int j = ri[tid + off];
                if (v > rv[tid] || (v == rv[tid] && j < ri[tid])) { rv[tid] = v; ri[tid] = j; }
            }
            __syncthreads();
        }
        if (tid == 0) { selv[m] = rv[0]; selj[m] = ri[0]; raw[ri[0]] = -3.4e38f; }
        __syncthreads();
    }

    // alphas
    if (warm) {
        float M0 = selv[0];                       // descending order -> max first
        float e = (tid < KMAX_) ? expf((selv[tid] - M0) * invT) : 0.f;
        float t = e;
        for (int o = 16; o; o >>= 1) t += __shfl_xor_sync(0xffffffffu, t, o);
        if ((tid & 31) == 0) rv[tid >> 5] = t;
        __syncthreads();
        if (tid == 0) sred = rv[0] + rv[1];
        __syncthreads();
        if (tid < KMAX_) out[b * KMAX_ + tid] = e / sred;
    } else {
        float e = (tid < KMAX_) ? selv[tid] : 0.f;
        float t = e;
        for (int o = 16; o; o >>= 1) t += __shfl_xor_sync(0xffffffffu, t, o);
        if ((tid & 31) == 0) rv[tid >> 5] = t;
        __syncthreads();
        if (tid == 0) sred = rv[0] + rv[1] + EPS_;
        __syncthreads();
        if (tid < KMAX_) out[b * KMAX_ + tid] = e / sred;
    }
    // global indices (cast to float, per output dtype)
    if (tid < KMAX_) {
        int j = selj[tid];
        int gidx = g_topc[b * MTOP_ + (j >> 7)] * NPC_ + (j & (NPC_ - 1));
        out[B_ * KMAX_ + b * KMAX_ + tid] = (float)gidx;
    }
}

// =====================================================================
// launch
// =====================================================================
extern "C" void kernel_launch(void* const* d_in, const int* in_sizes, int n_in,
                              void* d_out, int out_size) {
    (void)in_sizes; (void)n_in; (void)out_size;
    const float* z    = (const float*)d_in[0];
    const float* keys = (const float*)d_in[1];
    const float* WQ   = (const float*)d_in[2];
    const float* aw   = (const float*)d_in[3];
    const float* tau  = (const float*)d_in[4];
    const float* cen  = (const float*)d_in[5];
    const float* lam  = (const float*)d_in[6];
    const int*   warm = (const int*)d_in[7];
    float* out = (float*)d_out;

    cudaFuncSetAttribute(k_dense, cudaFuncAttributeMaxDynamicSharedMemorySize, SMEM_DENSE);

    k_weights<<<1, 32>>>(aw);
    k_queries<<<dim3(B_, S_), 256>>>(z, WQ);
    k_cnorm<<<S_ * C_, DK_>>>(cen);
    k_cscore<<<B_, 256>>>();
    k_topc<<<B_, 256>>>();
    k_dense<<<N_ / 128, 256, SMEM_DENSE>>>(keys);
    k_softfull<<<B_, 1024>>>(out);
    k_refine<<<B_, 256>>>(tau, lam, warm, out);
}

// round 15
// speedup vs baseline: 1.0177x; 1.0177x over previous
#include <cuda_runtime.h>
#include <math.h>
#include <stdint.h>

// ---- problem constants ----
#define S_    4
#define C_    1024
#define N_    131072
#define DK_   128
#define DA_   2048
#define MTOP_ 32
#define KMAX_ 64
#define B_    64
#define NPC_  (N_ / C_)        // 128
#define M_    (MTOP_ * NPC_)   // 4096
#define T_    1.0f
#define EPS_  1e-8f

// ---- device scratch (allocation-free rule: __device__ globals) ----
__device__ float g_w[S_];
__device__ float g_qn[S_ * B_ * DK_];            // [s][b][k]
__device__ float g_cn[S_ * C_ * DK_];            // normalized centroids
__device__ float g_cscore[B_ * C_];
__device__ int   g_topc[B_ * MTOP_];
__device__ float g_sif[(size_t)B_ * N_];         // s_i_full, 33.5 MB

// =====================================================================
// K0: w = softmax(aspect_weights)
// =====================================================================
__global__ void k_weights(const float* __restrict__ aw) {
    if (threadIdx.x == 0) {
        float m = aw[0];
        for (int s = 1; s < S_; ++s) m = fmaxf(m, aw[s]);
        float e[S_]; float sum = 0.f;
        for (int s = 0; s < S_; ++s) { e[s] = expf(aw[s] - m); sum += e[s]; }
        for (int s = 0; s < S_; ++s) g_w[s] = e[s] / sum;
    }
}

// =====================================================================
// K1: queries[b,s,:] = W_Q[s] @ z[b], then L2-normalize over k.
// grid (B_, S_), 256 threads.
// =====================================================================
__global__ void k_queries(const float* __restrict__ z, const float* __restrict__ WQ) {
    __shared__ float sz[DA_];
    __shared__ float qsh[DK_];
    __shared__ float red[9];
    const int b = blockIdx.x, s = blockIdx.y;
    const int tid = threadIdx.x, lane = tid & 31, warp = tid >> 5;

    for (int i = tid; i < DA_; i += 256) sz[i] = z[(size_t)b * DA_ + i];
    __syncthreads();

    const float4* sz4 = (const float4*)sz;
    for (int k = warp; k < DK_; k += 8) {
        const float4* Wr = (const float4*)(WQ + ((size_t)s * DK_ + k) * DA_);
        float acc = 0.f;
        for (int i = lane; i < DA_ / 4; i += 32) {
            float4 w4 = Wr[i], z4 = sz4[i];
            acc += w4.x * z4.x + w4.y * z4.y + w4.z * z4.z + w4.w * z4.w;
        }
        for (int o = 16; o; o >>= 1) acc += __shfl_xor_sync(0xffffffffu, acc, o);
        if (lane == 0) qsh[k] = acc;
    }
    __syncthreads();

    float v = (tid < DK_) ? qsh[tid] : 0.f;
    float ss = v * v;
    for (int o = 16; o; o >>= 1) ss += __shfl_xor_sync(0xffffffffu, ss, o);
    if (lane == 0) red[warp] = ss;
    __syncthreads();
    if (tid == 0) {
        float t = 0.f;
        for (int w = 0; w < 8; ++w) t += red[w];
        red[8] = 1.f / (sqrtf(t) + EPS_);
    }
    __syncthreads();
    if (tid < DK_) g_qn[((size_t)s * B_ + b) * DK_ + tid] = qsh[tid] * red[8];
}

// =====================================================================
// K2: normalize centroids. grid S_*C_, 128 threads.
// =====================================================================
__global__ void k_cnorm(const float* __restrict__ cen) {
    __shared__ float red[5];
    const int row = blockIdx.x, tid = threadIdx.x;
    float v = cen[(size_t)row * DK_ + tid];
    float ss = v * v;
    for (int o = 16; o; o >>= 1) ss += __shfl_xor_sync(0xffffffffu, ss, o);
    if ((tid & 31) == 0) red[tid >> 5] = ss;
    __syncthreads();
    if (tid == 0) {
        float t = red[0] + red[1] + red[2] + red[3];
        red[4] = 1.f / (sqrtf(t) + EPS_);
    }
    __syncthreads();
    g_cn[(size_t)row * DK_ + tid] = v * red[4];
}

// =====================================================================
// K3: c_score[b,c] = sum_s w_s * (qn[b,s] . cn[s,c]). grid B_, 256 thr.
// =====================================================================
__global__ void k_cscore() {
    __shared__ float qw[S_ * DK_];
    const int b = blockIdx.x, tid = threadIdx.x;
    for (int i = tid; i < S_ * DK_; i += 256) {
        int s = i >> 7;
        qw[i] = g_w[s] * g_qn[((size_t)s * B_ + b) * DK_ + (i & 127)];
    }
    __syncthreads();
    const float4* qw4 = (const float4*)qw;
    for (int c = tid; c < C_; c += 256) {
        float acc = 0.f;
        for (int s = 0; s < S_; ++s) {
            const float4* cp = (const float4*)(g_cn + ((size_t)s * C_ + c) * DK_);
#pragma unroll
            for (int i = 0; i < 32; ++i) {
                float4 cv = cp[i]; float4 qv = qw4[s * 32 + i];
                acc += cv.x * qv.x + cv.y * qv.y + cv.z * qv.z + cv.w * qv.w;
            }
        }
        g_cscore[b * C_ + c] = acc;
    }
}

// =====================================================================
// K4: top-32 clusters per batch row (descending, tie -> lowest index,
// matching jax.lax.top_k). grid B_, 256 threads.
// =====================================================================
__global__ void k_topc() {
    __shared__ float buf[C_];
    __shared__ float rv[256];
    __shared__ int   ri[256];
    const int b = blockIdx.x, tid = threadIdx.x;
    for (int i = tid; i < C_; i += 256) buf[i] = g_cscore[b * C_ + i];
    __syncthreads();
    for (int m = 0; m < MTOP_; ++m) {
        float bv = -3.4e38f; int bi = 0;
        for (int i = tid; i < C_; i += 256) {
            float v = buf[i];
            if (v > bv) { bv = v; bi = i; }       // ascending scan keeps earliest on ties
        }
        rv[tid] = bv; ri[tid] = bi;
        __syncthreads();
        for (int off = 128; off; off >>= 1) {
            if (tid < off) {
                float v = rv[tid + off]; int j = ri[tid + off];
                if (v > rv[tid] || (v == rv[tid] && j < ri[tid])) { rv[tid] = v; ri[tid] = j; }
            }
            __syncthreads();
        }
        if (tid == 0) { g_topc[b * MTOP_ + m] = ri[0]; buf[ri[0]] = -3.4e38f; }
        __syncthreads();
    }
}

// =====================================================================
// K5 (dominant): dense pass.
// s_i_full[b,n] = sum_s (w_s*qn[b,s]) . (key[s,n]/(||key||+eps))
// grid = N/128, 256 threads, 64x128 output tile, 4x8 per-thread tile.
// Keys tile XOR-swizzled in smem; keys normalized in place; queries
// pre-scaled by w_s so all 4 aspects accumulate into one register tile.
// =====================================================================
#define SMEM_DENSE ((128 * 68 + 128 * 128 + 128) * 4)

__global__ void __launch_bounds__(256, 2) k_dense(const float* __restrict__ keys) {
    extern __shared__ float sm[];
    float*  sA    = sm;                              // [k=128][68]  (pad 4, f4-aligned)
    float4* sB4   = (float4*)(sm + 128 * 68);        // 128 n x 32 kc, swizzled
    float*  snorm = sm + 128 * 68 + 128 * 128;       // [128]
    const int tid  = threadIdx.x;
    const int lane = tid & 31, warp = tid >> 5;
    const int n0   = blockIdx.x * 128;
    const int bx   = tid & 15, by = tid >> 4;
    const int sw   = bx & 7;

    float acc[4][8];
#pragma unroll
    for (int i = 0; i < 4; ++i)
#pragma unroll
        for (int j = 0; j < 8; ++j) acc[i][j] = 0.f;

    for (int s = 0; s < S_; ++s) {
        const float ws = g_w[s];
        // queries (pre-scaled by w_s), transposed: sA[k][b]
        for (int i = tid; i < B_ * DK_; i += 256) {
            int b = i >> 7, k = i & 127;
            sA[k * 68 + b] = ws * g_qn[((size_t)s * B_ + b) * DK_ + k];
        }
        // keys tile: [n][k], float4-coalesced, xor-swizzled on kc
        const float4* kp = (const float4*)(keys + ((size_t)s * N_ + n0) * DK_);
#pragma unroll
        for (int r = 0; r < 16; ++r) {
            int i = tid + r * 256;
            int n = i >> 5, kc = i & 31;
            sB4[n * 32 + (kc ^ ((n >> 3) & 7))] = kp[i];
        }
        __syncthreads();
        // per-key inverse norms: one warp per 16 n, lane = kc (conflict-free)
        for (int n = warp; n < 128; n += 8) {
            int sw2 = (n >> 3) & 7;
            float4 v = sB4[n * 32 + (lane ^ sw2)];
            float ssq = v.x * v.x + v.y * v.y + v.z * v.z + v.w * v.w;
            for (int o = 16; o; o >>= 1) ssq += __shfl_xor_sync(0xffffffffu, ssq, o);
            if (lane == 0) snorm[n] = 1.f / (sqrtf(ssq) + EPS_);
        }
        __syncthreads();
        // normalize keys in place
#pragma unroll
        for (int r = 0; r < 16; ++r) {
            int i = tid + r * 256;
            int n = i >> 5, kc = i & 31;
            int idx = n * 32 + (kc ^ ((n >> 3) & 7));
            float inv = snorm[n];
            float4 v = sB4[idx];
            v.x *= inv; v.y *= inv; v.z *= inv; v.w *= inv;
            sB4[idx] = v;
        }
        __syncthreads();
        // 64x128x128 FMA tile
        const float4* A4 = (const float4*)sA;        // 17 float4 per k-row
#pragma unroll 4
        for (int k4 = 0; k4 < 32; ++k4) {
            float4 kb[8];
#pragma unroll
            for (int j = 0; j < 8; ++j)
                kb[j] = sB4[(bx * 8 + j) * 32 + (k4 ^ sw)];
#pragma unroll
            for (int u = 0; u < 4; ++u) {
                float4 a = A4[(k4 * 4 + u) * 17 + by];
#pragma unroll
                for (int j = 0; j < 8; ++j) {
                    float kv = (u == 0) ? kb[j].x : (u == 1) ? kb[j].y : (u == 2) ? kb[j].z : kb[j].w;
                    acc[0][j] += a.x * kv;
                    acc[1][j] += a.y * kv;
                    acc[2][j] += a.z * kv;
                    acc[3][j] += a.w * kv;
                }
            }
        }
        __syncthreads();
    }
#pragma unroll
    for (int i = 0; i < 4; ++i) {
        int b = by * 4 + i;
        float4* dst = (float4*)(g_sif + (size_t)b * N_ + n0 + bx * 8);
        dst[0] = make_float4(acc[i][0], acc[i][1], acc[i][2], acc[i][3]);
        dst[1] = make_float4(acc[i][4], acc[i][5], acc[i][6], acc[i][7]);
    }
}

// =====================================================================
// K6: soft_full = softmax(s_i_full / T) per row. grid B_, 1024 threads.
// =====================================================================
__global__ void k_softfull(float* __restrict__ out) {
    __shared__ float red[32];
    __shared__ float sM, sS;
    const int b = blockIdx.x, tid = threadIdx.x, lane = tid & 31, warp = tid >> 5;
    const float* row = g_sif + (size_t)b * N_;
    float* o = out + (size_t)(2 * B_ * KMAX_) + (size_t)b * N_;
    const float invT = 1.0f / T_;

    float m = -3.4e38f;
    for (int i = tid; i < N_; i += 1024) m = fmaxf(m, row[i]);
    for (int off = 16; off; off >>= 1) m = fmaxf(m, __shfl_xor_sync(0xffffffffu, m, off));
    if (lane == 0) red[warp] = m;
    __syncthreads();
    if (tid == 0) {
        float t = red[0];
        for (int w = 1; w < 32; ++w) t = fmaxf(t, red[w]);
        sM = t;
    }
    __syncthreads();
    const float M = sM;

    float ssum = 0.f;
    for (int i = tid; i < N_; i += 1024) ssum += expf((row[i] - M) * invT);
    for (int off = 16; off; off >>= 1) ssum += __shfl_xor_sync(0xffffffffu, ssum, off);
    if (lane == 0) red[warp] = ssum;
    __syncthreads();
    if (tid == 0) {
        float t = 0.f;
        for (int w = 0; w < 32; ++w) t += red[w];
        sS = 1.f / t;
    }
    __syncthreads();
    const float rS = sS;
    for (int i = tid; i < N_; i += 1024) o[i] = expf((row[i] - M) * invT) * rS;
}

// =====================================================================
// K7: refine path. s_i = gather(s_i_full, cand_idx); gate+exp; normalize;
// top-64 (stable); alphas + global_idx. grid B_, 256 threads.
// =====================================================================
__global__ void k_refine(const float* __restrict__ taup, const float* __restrict__ lamp,
                         const int* __restrict__ warmp, float* __restrict__ out) {
    __shared__ float raw[M_];
    __shared__ float rv[256];
    __shared__ int   ri[256];
    __shared__ float selv[KMAX_];
    __shared__ int   selj[KMAX_];
    __shared__ float sred;
    const int b = blockIdx.x, tid = threadIdx.x;
    const int warm = *warmp;
    const float tau = *taup, lam = *lamp;
    const float invT = 1.0f / T_;

    for (int j = tid; j < M_; j += 256) {
        int c = g_topc[b * MTOP_ + (j >> 7)];
        int n = c * NPC_ + (j & (NPC_ - 1));
        float si = g_sif[(size_t)b * N_ + n];
        float val;
        if (warm) {
            val = si;
        } else {
            float gg = 1.f / (1.f + expf(-lam * (si - tau)));
            val = gg * expf(si * invT);
        }
        raw[j] = val;
    }
    __syncthreads();

    if (!warm) {
        float ps = 0.f;
        for (int j = tid; j < M_; j += 256) ps += raw[j];
        for (int o = 16; o; o >>= 1) ps += __shfl_xor_sync(0xffffffffu, ps, o);
        if ((tid & 31) == 0) rv[tid >> 5] = ps;
        __syncthreads();
        if (tid == 0) {
            float t = 0.f;
            for (int w = 0; w < 8; ++w) t += rv[w];
            sred = t;
        }
        __syncthreads();
        float S1 = sred + EPS_;
        for (int j = tid; j < M_; j += 256) raw[j] = raw[j] / S1;
        __syncthreads();
    }

    // top-64, descending, tie -> lowest index (matches jax.lax.top_k)
    for (int m = 0; m < KMAX_; ++m) {
        float bv = -3.4e38f; int bi = 0;
        for (int j = tid; j < M_; j += 256) {
            float v = raw[j];
            if (v > bv) { bv = v; bi = j; }
        }
        rv[tid] = bv; ri[tid] = bi;
        __syncthreads();
        for (int off = 128; off; off >>= 1) {
            if (tid < off) {
                float v = rv[tid + off]; int j = ri[tid + off];
                if (v > rv[tid] || (v == rv[tid] && j < ri[tid])) { rv[tid] = v; ri[tid] = j; }
            }
            __syncthreads();
        }
        if (tid == 0) { selv[m] = rv[0]; selj[m] = ri[0]; raw[ri[0]] = -3.4e38f; }
        __syncthreads();
    }

    // alphas
    if (warm) {
        float M0 = selv[0];                       // descending order -> max first
        float e = (tid < KMAX_) ? expf((selv[tid] - M0) * invT) : 0.f;
        float t = e;
        for (int o = 16; o; o >>= 1) t += __shfl_xor_sync(0xffffffffu, t, o);
        if ((tid & 31) == 0) rv[tid >> 5] = t;
        __syncthreads();
        if (tid == 0) sred = rv[0] + rv[1];
        __syncthreads();
        if (tid < KMAX_) out[b * KMAX_ + tid] = e / sred;
    } else {
        float e = (tid < KMAX_) ? selv[tid] : 0.f;
        float t = e;
        for (int o = 16; o; o >>= 1) t += __shfl_xor_sync(0xffffffffu, t, o);
        if ((tid & 31) == 0) rv[tid >> 5] = t;
        __syncthreads();
        if (tid == 0) sred = rv[0] + rv[1] + EPS_;
        __syncthreads();
        if (tid < KMAX_) out[b * KMAX_ + tid] = e / sred;
    }
    // global indices (cast to float, per output dtype)
    if (tid < KMAX_) {
        int j = selj[tid];
        int gidx = g_topc[b * MTOP_ + (j >> 7)] * NPC_ + (j & (NPC_ - 1));
        out[B_ * KMAX_ + b * KMAX_ + tid] = (float)gidx;
    }
}

// =====================================================================
// launch
// =====================================================================
extern "C" void kernel_launch(void* const* d_in, const int* in_sizes, int n_in,
                              void* d_out, int out_size) {
    (void)in_sizes; (void)n_in; (void)out_size;
    const float* z    = (const float*)d_in[0];
    const float* keys = (const float*)d_in[1];
    const float* WQ   = (const float*)d_in[2];
    const float* aw   = (const float*)d_in[3];
    const float* tau  = (const float*)d_in[4];
    const float* cen  = (const float*)d_in[5];
    const float* lam  = (const float*)d_in[6];
    const int*   warm = (const int*)d_in[7];
    float* out = (float*)d_out;

    cudaFuncSetAttribute(k_dense, cudaFuncAttributeMaxDynamicSharedMemorySize, SMEM_DENSE);

    k_weights<<<1, 32>>>(aw);
    k_queries<<<dim3(B_, S_), 256>>>(z, WQ);
    k_cnorm<<<S_ * C_, DK_>>>(cen);
    k_cscore<<<B_, 256>>>();
    k_topc<<<B_, 256>>>();
    k_dense<<<N_ / 128, 256, SMEM_DENSE>>>(keys);
    k_softfull<<<B_, 1024>>>(out);
    k_refine<<<B_, 256>>>(tau, lam, warm, out);
}

// round 16
// speedup vs baseline: 1.1366x; 1.1169x over previous
#include <cuda_runtime.h>
#include <math.h>
#include <stdint.h>

// ---- problem constants ----
#define S_    4
#define C_    1024
#define N_    131072
#define DK_   128
#define DA_   2048
#define MTOP_ 32
#define KMAX_ 64
#define B_    64
#define NPC_  (N_ / C_)        // 128
#define M_    (MTOP_ * NPC_)   // 4096
#define T_    1.0f
#define EPS_  1e-8f

// ---- device scratch ----
__device__ float g_w[S_];
__device__ float g_qn[S_ * B_ * DK_];            // [s][b][k]
__device__ float g_cn[S_ * C_ * DK_];
__device__ float g_cscore[B_ * C_];
__device__ int   g_topc[B_ * MTOP_];
__device__ float g_sif[(size_t)B_ * N_];         // s_i_full, 33.5 MB
__device__ float g_esum[B_];

// ---- fast exp on the FMA pipe (rel err ~2e-7 on |x| < 10) ----
__device__ __forceinline__ float fexp(float x) {
    float t = fmaf(x, 1.4426950408889634f, 12582912.0f);
    float n = t - 12582912.0f;
    float r = fmaf(n, -0.693145751953125f, x);
    r = fmaf(n, -1.42860677e-06f, r);
    float p = fmaf(1.9841270e-4f, r, 1.3888889e-3f);
    p = fmaf(p, r, 8.3333333e-3f);
    p = fmaf(p, r, 4.1666667e-2f);
    p = fmaf(p, r, 1.6666667e-1f);
    p = fmaf(p, r, 0.5f);
    p = fmaf(p, r, 1.0f);
    p = fmaf(p, r, 1.0f);
    int i = (int)n;
    return p * __int_as_float((i + 127) << 23);
}

// ordered-float packed key: max key == max value, tie -> lowest index
__device__ __forceinline__ unsigned long long packkey(float v, int j) {
    unsigned u = __float_as_uint(v);
    u = (u & 0x80000000u) ? ~u : (u | 0x80000000u);
    return ((unsigned long long)u << 32) | (unsigned)(~j);
}

// =====================================================================
// K0: w = softmax(aspect_weights)
// =====================================================================
__global__ void k_weights(const float* __restrict__ aw) {
    if (threadIdx.x == 0) {
        float m = aw[0];
        for (int s = 1; s < S_; ++s) m = fmaxf(m, aw[s]);
        float e[S_]; float sum = 0.f;
        for (int s = 0; s < S_; ++s) { e[s] = expf(aw[s] - m); sum += e[s]; }
        for (int s = 0; s < S_; ++s) g_w[s] = e[s] / sum;
    }
}

// =====================================================================
// K1: queries + L2 normalize. 4 batch rows per block share W_Q loads.
// grid (B_/4, S_), 256 threads.
// =====================================================================
__global__ void k_queries(const float* __restrict__ z, const float* __restrict__ WQ) {
    __shared__ float4 sz4[4][DA_ / 4];
    __shared__ float qsh[4][DK_];
    const int b0 = blockIdx.x * 4, s = blockIdx.y;
    const int tid = threadIdx.x, lane = tid & 31, warp = tid >> 5;

    for (int i = tid; i < 4 * (DA_ / 4); i += 256) {
        int row = i >> 9, col = i & 511;
        sz4[row][col] = ((const float4*)z)[(size_t)(b0 + row) * (DA_ / 4) + col];
    }
    __syncthreads();

    for (int k = warp; k < DK_; k += 8) {
        const float4* Wr = (const float4*)(WQ + ((size_t)s * DK_ + k) * DA_);
        float a0 = 0.f, a1 = 0.f, a2 = 0.f, a3 = 0.f;
        for (int i = lane; i < DA_ / 4; i += 32) {
            float4 w4 = Wr[i];
            float4 z0 = sz4[0][i], z1 = sz4[1][i], z2 = sz4[2][i], z3 = sz4[3][i];
            a0 += w4.x * z0.x + w4.y * z0.y + w4.z * z0.z + w4.w * z0.w;
            a1 += w4.x * z1.x + w4.y * z1.y + w4.z * z1.z + w4.w * z1.w;
            a2 += w4.x * z2.x + w4.y * z2.y + w4.z * z2.z + w4.w * z2.w;
            a3 += w4.x * z3.x + w4.y * z3.y + w4.z * z3.z + w4.w * z3.w;
        }
        for (int o = 16; o; o >>= 1) {
            a0 += __shfl_xor_sync(0xffffffffu, a0, o);
            a1 += __shfl_xor_sync(0xffffffffu, a1, o);
            a2 += __shfl_xor_sync(0xffffffffu, a2, o);
            a3 += __shfl_xor_sync(0xffffffffu, a3, o);
        }
        if (lane == 0) { qsh[0][k] = a0; qsh[1][k] = a1; qsh[2][k] = a2; qsh[3][k] = a3; }
    }
    __syncthreads();

    if (warp < 4) {
        int b = b0 + warp;
        float ssq = 0.f;
        for (int k = lane; k < DK_; k += 32) { float v = qsh[warp][k]; ssq += v * v; }
        for (int o = 16; o; o >>= 1) ssq += __shfl_xor_sync(0xffffffffu, ssq, o);
        float inv = 1.f / (sqrtf(ssq) + EPS_);
        for (int k = lane; k < DK_; k += 32)
            g_qn[((size_t)s * B_ + b) * DK_ + k] = qsh[warp][k] * inv;
    }
}

// =====================================================================
// K2: normalize centroids. grid S_*C_, 128 threads.
// =====================================================================
__global__ void k_cnorm(const float* __restrict__ cen) {
    __shared__ float red[5];
    const int row = blockIdx.x, tid = threadIdx.x;
    float v = cen[(size_t)row * DK_ + tid];
    float ss = v * v;
    for (int o = 16; o; o >>= 1) ss += __shfl_xor_sync(0xffffffffu, ss, o);
    if ((tid & 31) == 0) red[tid >> 5] = ss;
    __syncthreads();
    if (tid == 0) {
        float t = red[0] + red[1] + red[2] + red[3];
        red[4] = 1.f / (sqrtf(t) + EPS_);
    }
    __syncthreads();
    g_cn[(size_t)row * DK_ + tid] = v * red[4];
}

// =====================================================================
// K3: c_score. grid (B_, 8), 128 threads, 1 c per thread, 4 acc chains.
// =====================================================================
__global__ void k_cscore() {
    __shared__ float qw[S_ * DK_];
    const int b = blockIdx.x, tid = threadIdx.x;
    for (int i = tid; i < S_ * DK_; i += 128) {
        int s = i >> 7;
        qw[i] = g_w[s] * g_qn[((size_t)s * B_ + b) * DK_ + (i & 127)];
    }
    __syncthreads();
    const int c = blockIdx.y * 128 + tid;
    const float4* qw4 = (const float4*)qw;
    float acc = 0.f;
#pragma unroll
    for (int s = 0; s < S_; ++s) {
        const float4* cp = (const float4*)(g_cn + ((size_t)s * C_ + c) * DK_);
        float a0 = 0.f, a1 = 0.f, a2 = 0.f, a3 = 0.f;
#pragma unroll
        for (int i = 0; i < 32; i += 4) {
            float4 c0 = cp[i],     q0 = qw4[s * 32 + i];
            float4 c1 = cp[i + 1], q1 = qw4[s * 32 + i + 1];
            float4 c2 = cp[i + 2], q2 = qw4[s * 32 + i + 2];
            float4 c3 = cp[i + 3], q3 = qw4[s * 32 + i + 3];
            a0 += c0.x * q0.x + c0.y * q0.y + c0.z * q0.z + c0.w * q0.w;
            a1 += c1.x * q1.x + c1.y * q1.y + c1.z * q1.z + c1.w * q1.w;
            a2 += c2.x * q2.x + c2.y * q2.y + c2.z * q2.z + c2.w * q2.w;
            a3 += c3.x * q3.x + c3.y * q3.y + c3.z * q3.z + c3.w * q3.w;
        }
        acc += (a0 + a1) + (a2 + a3);
    }
    g_cscore[b * C_ + c] = acc;
}

// =====================================================================
// K4: top-32 clusters via packed u64 keys. grid B_, 256 threads.
// =====================================================================
__global__ void k_topc() {
    __shared__ unsigned long long wk[8];
    __shared__ unsigned long long winner;
    const int b = blockIdx.x, tid = threadIdx.x, lane = tid & 31, warp = tid >> 5;
    unsigned long long key[4];
#pragma unroll
    for (int slot = 0; slot < 4; ++slot) {
        int j = slot * 256 + tid;
        key[slot] = packkey(g_cscore[b * C_ + j], j);
    }
    for (int m = 0; m < MTOP_; ++m) {
        unsigned long long loc = key[0];
#pragma unroll
        for (int slot = 1; slot < 4; ++slot) if (key[slot] > loc) loc = key[slot];
        for (int o = 16; o; o >>= 1) {
            unsigned long long t = __shfl_xor_sync(0xffffffffu, loc, o);
            if (t > loc) loc = t;
        }
        if (lane == 0) wk[warp] = loc;
        __syncthreads();
        if (tid == 0) {
            unsigned long long w0 = wk[0];
            for (int i = 1; i < 8; ++i) if (wk[i] > w0) w0 = wk[i];
            winner = w0;
            g_topc[b * MTOP_ + m] = (int)(~(unsigned)w0);
        }
        __syncthreads();
        int j = (int)(~(unsigned)winner);
        if ((j & 255) == tid) key[j >> 8] = 0ull;
    }
}

// =====================================================================
// K5 (dominant): dense pass — unchanged from the passing kernel.
// =====================================================================
#define SMEM_DENSE ((128 * 68 + 128 * 128 + 128) * 4)

__global__ void __launch_bounds__(256, 2) k_dense(const float* __restrict__ keys) {
    extern __shared__ float sm[];
    float*  sA    = sm;                              // [k=128][68]
    float4* sB4   = (float4*)(sm + 128 * 68);        // 128 n x 32 kc, swizzled
    float*  snorm = sm + 128 * 68 + 128 * 128;
    const int tid  = threadIdx.x;
    const int lane = tid & 31, warp = tid >> 5;
    const int n0   = blockIdx.x * 128;
    const int bx   = tid & 15, by = tid >> 4;
    const int sw   = bx & 7;

    float acc[4][8];
#pragma unroll
    for (int i = 0; i < 4; ++i)
#pragma unroll
        for (int j = 0; j < 8; ++j) acc[i][j] = 0.f;

    for (int s = 0; s < S_; ++s) {
        const float ws = g_w[s];
        for (int i = tid; i < B_ * DK_; i += 256) {
            int b = i >> 7, k = i & 127;
            sA[k * 68 + b] = ws * g_qn[((size_t)s * B_ + b) * DK_ + k];
        }
        const float4* kp = (const float4*)(keys + ((size_t)s * N_ + n0) * DK_);
#pragma unroll
        for (int r = 0; r < 16; ++r) {
            int i = tid + r * 256;
            int n = i >> 5, kc = i & 31;
            sB4[n * 32 + (kc ^ ((n >> 3) & 7))] = kp[i];
        }
        __syncthreads();
        for (int n = warp; n < 128; n += 8) {
            int sw2 = (n >> 3) & 7;
            float4 v = sB4[n * 32 + (lane ^ sw2)];
            float ssq = v.x * v.x + v.y * v.y + v.z * v.z + v.w * v.w;
            for (int o = 16; o; o >>= 1) ssq += __shfl_xor_sync(0xffffffffu, ssq, o);
            if (lane == 0) snorm[n] = 1.f / (sqrtf(ssq) + EPS_);
        }
        __syncthreads();
#pragma unroll
        for (int r = 0; r < 16; ++r) {
            int i = tid + r * 256;
            int n = i >> 5, kc = i & 31;
            int idx = n * 32 + (kc ^ ((n >> 3) & 7));
            float inv = snorm[n];
            float4 v = sB4[idx];
            v.x *= inv; v.y *= inv; v.z *= inv; v.w *= inv;
            sB4[idx] = v;
        }
        __syncthreads();
        const float4* A4 = (const float4*)sA;
#pragma unroll 4
        for (int k4 = 0; k4 < 32; ++k4) {
            float4 kb[8];
#pragma unroll
            for (int j = 0; j < 8; ++j)
                kb[j] = sB4[(bx * 8 + j) * 32 + (k4 ^ sw)];
#pragma unroll
            for (int u = 0; u < 4; ++u) {
                float4 a = A4[(k4 * 4 + u) * 17 + by];
#pragma unroll
                for (int j = 0; j < 8; ++j) {
                    float kv = (u == 0) ? kb[j].x : (u == 1) ? kb[j].y : (u == 2) ? kb[j].z : kb[j].w;
                    acc[0][j] += a.x * kv;
                    acc[1][j] += a.y * kv;
                    acc[2][j] += a.z * kv;
                    acc[3][j] += a.w * kv;
                }
            }
        }
        __syncthreads();
    }
#pragma unroll
    for (int i = 0; i < 4; ++i) {
        int b = by * 4 + i;
        float4* dst = (float4*)(g_sif + (size_t)b * N_ + n0 + bx * 8);
        dst[0] = make_float4(acc[i][0], acc[i][1], acc[i][2], acc[i][3]);
        dst[1] = make_float4(acc[i][4], acc[i][5], acc[i][6], acc[i][7]);
    }
}

// =====================================================================
// K6a: per-row exp-sum (deterministic, no max pass: |scores| <= ~1.05,
// softmax is shift-invariant). grid B_, 1024 threads.
// =====================================================================
__global__ void k_esum() {
    __shared__ float red[32];
    const int b = blockIdx.x, tid = threadIdx.x, lane = tid & 31, warp = tid >> 5;
    const float4* row4 = (const float4*)(g_sif + (size_t)b * N_);
    const float invT = 1.0f / T_;
    float s = 0.f;
    for (int i = tid; i < N_ / 4; i += 1024) {
        float4 v = row4[i];
        s += fexp(v.x * invT) + fexp(v.y * invT) + fexp(v.z * invT) + fexp(v.w * invT);
    }
    for (int o = 16; o; o >>= 1) s += __shfl_xor_sync(0xffffffffu, s, o);
    if (lane == 0) red[warp] = s;
    __syncthreads();
    if (tid == 0) {
        float t = 0.f;
        for (int w = 0; w < 32; ++w) t += red[w];
        g_esum[b] = t;
    }
}

// =====================================================================
// K6b: soft_full write: out = exp(x)/sum. grid 8192, 256 threads.
// =====================================================================
__global__ void k_swrite(float* __restrict__ out) {
    const int i4 = blockIdx.x * 256 + threadIdx.x;     // one float4 per thread
    const int b = i4 >> 15;
    const float inv = 1.f / g_esum[b];
    const float invT = 1.0f / T_;
    float4 v = ((const float4*)g_sif)[i4];
    float4 r = make_float4(fexp(v.x * invT) * inv, fexp(v.y * invT) * inv,
                           fexp(v.z * invT) * inv, fexp(v.w * invT) * inv);
    ((float4*)out)[2 * B_ * KMAX_ / 4 + i4] = r;
}

// =====================================================================
// K7: refine. gather s_i from dense output; gate+exp; top-64 via packed
// keys; alphas + global_idx. grid B_, 256 threads.
// =====================================================================
__global__ void k_refine(const float* __restrict__ taup, const float* __restrict__ lamp,
                         const int* __restrict__ warmp, float* __restrict__ out) {
    __shared__ float raw[M_];
    __shared__ unsigned long long wk[8];
    __shared__ unsigned long long winner;
    __shared__ float selv[KMAX_];
    __shared__ int   selj[KMAX_];
    __shared__ float red[8];
    __shared__ float sden;
    const int b = blockIdx.x, tid = threadIdx.x, lane = tid & 31, warp = tid >> 5;
    const int warm = *warmp;
    const float tau = *taup, lam = *lamp;
    const float invT = 1.0f / T_;

    unsigned long long key[16];
#pragma unroll
    for (int slot = 0; slot < 16; ++slot) {
        int j = slot * 256 + tid;
        int c = g_topc[b * MTOP_ + (j >> 7)];
        int n = c * NPC_ + (j & (NPC_ - 1));
        float si = g_sif[(size_t)b * N_ + n];
        float val;
        if (warm) {
            val = si;
        } else {
            float gg = 1.f / (1.f + fexp(-lam * (si - tau)));
            val = gg * fexp(si * invT);
        }
        raw[j] = val;
        key[slot] = packkey(val, j);
    }
    __syncthreads();

    // total sum for the non-warm normalization (order-preserving; applied later)
    float S1 = 1.f;
    if (!warm) {
        float ps = 0.f;
#pragma unroll
        for (int slot = 0; slot < 16; ++slot) ps += raw[slot * 256 + tid];
        for (int o = 16; o; o >>= 1) ps += __shfl_xor_sync(0xffffffffu, ps, o);
        if (lane == 0) red[warp] = ps;
        __syncthreads();
        if (tid == 0) {
            float t = 0.f;
            for (int w = 0; w < 8; ++w) t += red[w];
            sden = t;
        }
        __syncthreads();
        S1 = sden + EPS_;
        __syncthreads();
    }

    // top-64, descending, tie -> lowest index
    for (int m = 0; m < KMAX_; ++m) {
        unsigned long long loc = key[0];
#pragma unroll
        for (int slot = 1; slot < 16; ++slot) if (key[slot] > loc) loc = key[slot];
        for (int o = 16; o; o >>= 1) {
            unsigned long long t = __shfl_xor_sync(0xffffffffu, loc, o);
            if (t > loc) loc = t;
        }
        if (lane == 0) wk[warp] = loc;
        __syncthreads();
        if (tid == 0) {
            unsigned long long w0 = wk[0];
            for (int i = 1; i < 8; ++i) if (wk[i] > w0) w0 = wk[i];
            winner = w0;
            int j = (int)(~(unsigned)w0);
            selj[m] = j;
            selv[m] = raw[j];
        }
        __syncthreads();
        int j = (int)(~(unsigned)winner);
        if ((j & 255) == tid) key[j >> 8] = 0ull;
    }
    __syncthreads();

    // alphas
    float e = 0.f;
    if (tid < KMAX_) {
        if (warm) e = fexp((selv[tid] - selv[0]) * invT);
        else      e = selv[tid] / S1;
    }
    float t = e;
    for (int o = 16; o; o >>= 1) t += __shfl_xor_sync(0xffffffffu, t, o);
    if (lane == 0) red[warp] = t;
    __syncthreads();
    if (tid == 0) sden = red[0] + red[1] + (warm ? 0.f : EPS_);
    __syncthreads();
    if (tid < KMAX_) {
        out[b * KMAX_ + tid] = e / sden;
        int j = selj[tid];
        int gidx = g_topc[b * MTOP_ + (j >> 7)] * NPC_ + (j & (NPC_ - 1));
        out[B_ * KMAX_ + b * KMAX_ + tid] = (float)gidx;
    }
}

// =====================================================================
// launch
// =====================================================================
extern "C" void kernel_launch(void* const* d_in, const int* in_sizes, int n_in,
                              void* d_out, int out_size) {
    (void)in_sizes; (void)n_in; (void)out_size;
    const float* z    = (const float*)d_in[0];
    const float* keys = (const float*)d_in[1];
    const float* WQ   = (const float*)d_in[2];
    const float* aw   = (const float*)d_in[3];
    const float* tau  = (const float*)d_in[4];
    const float* cen  = (const float*)d_in[5];
    const float* lam  = (const float*)d_in[6];
    const int*   warm = (const int*)d_in[7];
    float* out = (float*)d_out;

    cudaFuncSetAttribute(k_dense, cudaFuncAttributeMaxDynamicSharedMemorySize, SMEM_DENSE);

    k_weights<<<1, 32>>>(aw);
    k_queries<<<dim3(B_ / 4, S_), 256>>>(z, WQ);
    k_cnorm<<<S_ * C_, DK_>>>(cen);
    k_cscore<<<dim3(B_, 8), 128>>>();
    k_topc<<<B_, 256>>>();
    k_dense<<<N_ / 128, 256, SMEM_DENSE>>>(keys);
    k_esum<<<B_, 1024>>>();
    k_swrite<<<(B_ * N_) / (4 * 256), 256>>>(out);
    k_refine<<<B_, 256>>>(tau, lam, warm, out);
}